// round 17
// baseline (speedup 1.0000x reference)
#include <cuda_runtime.h>
#include <cuda_fp16.h>
#include <math.h>
#include <stdint.h>

// Problem constants
#define NB   2
#define LSEQ 1024
#define HH   8
#define DHD  64
#define DDIM 512
#define TCH  128
#define NCH  8
#define NHH  16
#define MROWS (NB*LSEQ)    // 2048
#define SROW 8320          // per-chunk state: 128x64 S + 128 den

// Device scratch (no cudaMalloc allowed)
__device__ float g_Q[MROWS*DDIM];
__device__ float g_K[MROWS*DDIM];
__device__ float g_V[MROWS*DDIM];
__device__ float g_S[NHH*NCH*SROW];
// fp16 copies for the projection GEMM
__device__ __half g_hq[MROWS*DDIM];
__device__ __half g_hk[MROWS*DDIM];
__device__ __half g_hWq[DDIM*DDIM];
__device__ __half g_hWk[DDIM*DDIM];
__device__ __half g_hWv[DDIM*DDIM];

__device__ __forceinline__ float softplus_f(float x) {
    return fmaxf(x, 0.0f) + log1pf(expf(-fabsf(x)));
}

// ---------------------------------------------------------------------------
// Primitives (compile clean for compute_103 baseline target)
// ---------------------------------------------------------------------------
__device__ __forceinline__ uint32_t smem_u32(const void* p) {
    uint32_t a;
    asm("{ .reg .u64 t; cvta.to.shared.u64 t, %1; cvt.u32.u64 %0, t; }"
        : "=r"(a) : "l"(p));
    return a;
}
#define CP_ASYNC16(dst, src) \
    asm volatile("cp.async.cg.shared.global [%0], [%1], 16;" :: "r"(dst), "l"(src))
#define CP_COMMIT()  asm volatile("cp.async.commit_group;" ::: "memory")
#define CP_WAIT(n)   asm volatile("cp.async.wait_group %0;" :: "n"(n) : "memory")

__device__ __forceinline__ void mma_f16(float* d, const uint32_t* a, const uint32_t* b) {
    asm volatile(
        "mma.sync.aligned.m16n8k16.row.col.f32.f16.f16.f32 "
        "{%0,%1,%2,%3}, {%4,%5,%6,%7}, {%8,%9}, {%0,%1,%2,%3};"
        : "+f"(d[0]), "+f"(d[1]), "+f"(d[2]), "+f"(d[3])
        : "r"(a[0]), "r"(a[1]), "r"(a[2]), "r"(a[3]), "r"(b[0]), "r"(b[1]));
}
__device__ __forceinline__ uint32_t pack_h2(float lo, float hi) {
    __half2 h = __floats2half2_rn(lo, hi);
    return *(uint32_t*)&h;
}
// half-layout swizzle (b32 units, 16 b32 per row)
__device__ __forceinline__ int hswz(int row, int c) { return c ^ (((row >> 1) & 3) << 2); }

// Strides (b32 units; ==8 mod 32 -> conflict-free fragment LDS)
#define SH  136
#define SVH 72

// ---------------------------------------------------------------------------
// Kernel 0: convert inputs to fp16 (rne). y: 0=query, 1=key, 2=Wq, 3=Wk, 4=Wv
// ---------------------------------------------------------------------------
__global__ __launch_bounds__(256) void conv_half_kernel(
        const float* __restrict__ query, const float* __restrict__ key,
        const float* __restrict__ Wq, const float* __restrict__ Wk,
        const float* __restrict__ Wv) {
    const int y = blockIdx.y;
    const float* src; __half* dst; int n4;
    switch (y) {
        case 0: src = query; dst = g_hq;  n4 = MROWS*DDIM/4; break;
        case 1: src = key;   dst = g_hk;  n4 = MROWS*DDIM/4; break;
        case 2: src = Wq;    dst = g_hWq; n4 = DDIM*DDIM/4;  break;
        case 3: src = Wk;    dst = g_hWk; n4 = DDIM*DDIM/4;  break;
        default: src = Wv;   dst = g_hWv; n4 = DDIM*DDIM/4;  break;
    }
    int idx = blockIdx.x * 256 + threadIdx.x;
    if (idx < n4) {
        float4 v = ((const float4*)src)[idx];
        uint2 pk;
        pk.x = pack_h2(v.x, v.y);
        pk.y = pack_h2(v.z, v.w);
        ((uint2*)dst)[idx] = pk;
    }
}

// ---------------------------------------------------------------------------
// Kernel G: projection GEMM fp16. Block tile 128x128, 8 warps (64x32 each),
// BK=32 halves, 4-stage cp.async ring (issue depth 3), 16KB/stage = 64KB.
// ---------------------------------------------------------------------------
__global__ __launch_bounds__(256, 2) void proj_mma_kernel() {
    extern __shared__ __align__(16) uint32_t smP[];
    // stage s (4096 b32): A 128x16 b32 at +0, B 128x16 b32 at +2048

    const int which = blockIdx.z;
    const __half* __restrict__ A = (which == 0) ? g_hq : g_hk;
    const __half* __restrict__ B = (which == 0) ? g_hWq : (which == 1) ? g_hWk : g_hWv;
    float* __restrict__ out = (which == 0) ? g_Q : (which == 1) ? g_K : g_V;
    const int am0 = blockIdx.x * 128;
    const int bn0 = blockIdx.y * 128;

    const int tid = threadIdx.x;
    const int wid = tid >> 5, lane = tid & 31;
    const int gid = lane >> 2, tid4 = lane & 3;
    const int m0 = (wid & 1) * 64;
    const int n0 = (wid >> 1) * 32;

    float acc[4][4][4];
#pragma unroll
    for (int i = 0; i < 4; i++)
#pragma unroll
        for (int j = 0; j < 4; j++)
#pragma unroll
            for (int q = 0; q < 4; q++) acc[i][j][q] = 0.0f;

    const uint32_t sbase = smem_u32(smP);

    auto issue_stage = [&](int kt, int buf) {
        const int k0 = kt * 32;
        uint32_t sa = sbase + buf * 4096 * 4;
        uint32_t sb = sa + 2048 * 4;
#pragma unroll
        for (int i = 0; i < 2; i++) {
            int f4 = tid + 256 * i;
            int row = f4 >> 2;
            int cq  = (f4 & 3) << 2;
            int soff = (row * 16 + hswz(row, cq)) * 4;
            CP_ASYNC16(sa + soff, &A[(size_t)(am0 + row) * DDIM + k0 + cq * 2]);
        }
#pragma unroll
        for (int i = 0; i < 2; i++) {
            int f4 = tid + 256 * i;
            int row = f4 >> 2;
            int cq  = (f4 & 3) << 2;
            int soff = (row * 16 + hswz(row, cq)) * 4;
            CP_ASYNC16(sb + soff, &B[(size_t)(bn0 + row) * DDIM + k0 + cq * 2]);
        }
        CP_COMMIT();
    };

    issue_stage(0, 0);
    issue_stage(1, 1);
    issue_stage(2, 2);

    for (int kt = 0; kt < 16; kt++) {
        if (kt < 13) issue_stage(kt + 3, (kt + 3) & 3);
        CP_WAIT(3);
        __syncthreads();

        const uint32_t* sA = smP + (kt & 3) * 4096;
        const uint32_t* sB = sA + 2048;
#pragma unroll
        for (int step = 0; step < 2; step++) {
            const int s8 = step * 8;
            uint32_t af[4][4];
#pragma unroll
            for (int mt = 0; mt < 4; mt++) {
                int r = m0 + mt * 16 + gid;
                af[mt][0] = sA[r * 16 + hswz(r, s8 + tid4)];
                af[mt][1] = sA[(r + 8) * 16 + hswz(r + 8, s8 + tid4)];
                af[mt][2] = sA[r * 16 + hswz(r, s8 + tid4 + 4)];
                af[mt][3] = sA[(r + 8) * 16 + hswz(r + 8, s8 + tid4 + 4)];
            }
            uint32_t bf[4][2];
#pragma unroll
            for (int nt = 0; nt < 4; nt++) {
                int nn = n0 + nt * 8 + gid;
                bf[nt][0] = sB[nn * 16 + hswz(nn, s8 + tid4)];
                bf[nt][1] = sB[nn * 16 + hswz(nn, s8 + tid4 + 4)];
            }
#pragma unroll
            for (int mt = 0; mt < 4; mt++)
#pragma unroll
                for (int nt = 0; nt < 4; nt++)
                    mma_f16(acc[mt][nt], af[mt], bf[nt]);
        }
        __syncthreads();
    }

    const bool act = (which < 2);
#pragma unroll
    for (int mt = 0; mt < 4; mt++) {
#pragma unroll
        for (int nt = 0; nt < 4; nt++) {
            int row = am0 + m0 + mt * 16 + gid;
            int col = bn0 + n0 + nt * 8 + tid4 * 2;
            float v0 = acc[mt][nt][0], v1 = acc[mt][nt][1];
            float v2 = acc[mt][nt][2], v3 = acc[mt][nt][3];
            if (act) {
                v0 = softplus_f(v0); v1 = softplus_f(v1);
                v2 = softplus_f(v2); v3 = softplus_f(v3);
            }
            *(float2*)&out[(size_t)row * DDIM + col] = make_float2(v0, v1);
            *(float2*)&out[(size_t)(row + 8) * DDIM + col] = make_float2(v2, v3);
        }
    }
}

// ---------------------------------------------------------------------------
// Kernel B: per-chunk KV state via fp16 mma. k-dim = t packed as t-pairs.
// sKfh[tp][f] = (Kf[2tp][f], Kf[2tp+1][f]); sVh[tp][e] = (V[2tp][e],V[2tp+1][e]).
// Interleaved feature order (f=2d cos, 2d+1 sin). 512 threads, 16 warps 32x16.
// smem: sKfh 64x136 (8704 b32) | sVh 64x72 (4608 b32) = 53248 B.
// ---------------------------------------------------------------------------
__global__ __launch_bounds__(512) void chunk_state_kernel(const float* __restrict__ pw) {
    extern __shared__ __align__(16) uint32_t smC[];
    uint32_t* sKfh = smC;           // [tp][f]
    uint32_t* sVh  = smC + 8704;    // [tp][e]

    const int nh = blockIdx.x, c = blockIdx.y;
    const int n = nh >> 3, h = nh & 7;
    const int tid = threadIdx.x;
    const int wid = tid >> 5, lane = tid & 31;
    const int gid = lane >> 2, tid4 = lane & 3;

    for (int idx = tid; idx < 64*64; idx += 512) {
        int tp = idx >> 6, di = idx & 63;
        int t0 = c * TCH + 2*tp;
        int gb0 = ((n << 10) + t0) * DDIM + (h << 6) + di;
        float k0 = g_K[gb0],        v0 = g_V[gb0];
        float k1 = g_K[gb0 + DDIM], v1 = g_V[gb0 + DDIM];
        float w  = pw[(h << 6) + di];
        float s0, c0, s1, c1;
        sincosf((float)t0 * w, &s0, &c0);
        sincosf((float)(t0 + 1) * w, &s1, &c1);
        sKfh[tp*SH + 2*di]     = pack_h2(k0 * c0, k1 * c1);
        sKfh[tp*SH + 2*di + 1] = pack_h2(k0 * s0, k1 * s1);
        sVh[tp*SVH + di]       = pack_h2(v0, v1);
    }
    __syncthreads();

    const int m0 = (wid & 3) * 32;
    const int n0 = (wid >> 2) * 16;
    float acc[2][2][4] = {};
#pragma unroll
    for (int s = 0; s < 8; s++) {
        const int kp0 = s * 8 + tid4, kp1 = kp0 + 4;
        uint32_t af[2][4];
#pragma unroll
        for (int mt = 0; mt < 2; mt++) {
            int r = m0 + mt * 16 + gid;
            af[mt][0] = sKfh[kp0*SH + r];
            af[mt][1] = sKfh[kp0*SH + r + 8];
            af[mt][2] = sKfh[kp1*SH + r];
            af[mt][3] = sKfh[kp1*SH + r + 8];
        }
        uint32_t bf[2][2];
#pragma unroll
        for (int nt = 0; nt < 2; nt++) {
            int nn = n0 + nt * 8 + gid;
            bf[nt][0] = sVh[kp0*SVH + nn];
            bf[nt][1] = sVh[kp1*SVH + nn];
        }
#pragma unroll
        for (int mt = 0; mt < 2; mt++)
#pragma unroll
            for (int nt = 0; nt < 2; nt++)
                mma_f16(acc[mt][nt], af[mt], bf[nt]);
    }
    size_t base = (size_t)(nh * NCH + c) * SROW;
#pragma unroll
    for (int mt = 0; mt < 2; mt++) {
#pragma unroll
        for (int nt = 0; nt < 2; nt++) {
            int f = m0 + mt * 16 + gid;
            int e = n0 + nt * 8 + tid4 * 2;
            *(float2*)&g_S[base + (size_t)f * 64 + e] =
                make_float2(acc[mt][nt][0], acc[mt][nt][1]);
            *(float2*)&g_S[base + (size_t)(f + 8) * 64 + e] =
                make_float2(acc[mt][nt][2], acc[mt][nt][3]);
        }
    }
    if (tid < 128) {
        float s = 0.0f;
        for (int tp = 0; tp < 64; tp++) {
            __half2 hv = *(__half2*)&sKfh[tp*SH + tid];
            s += __low2float(hv) + __high2float(hv);
        }
        g_S[base + 8192 + tid] = s;
    }
}

// ---------------------------------------------------------------------------
// Kernel D: per-chunk output — fp16 MMA, interleaved pairs (as r15).
// ---------------------------------------------------------------------------
__global__ __launch_bounds__(1024, 1) void attn_out_kernel(
        const float* __restrict__ pw, const float* __restrict__ pb,
        const float* __restrict__ coeff, float* __restrict__ out) {
    extern __shared__ __align__(16) uint32_t smU[];
    uint32_t* sQTh = smU;            // [d pair][t]
    uint32_t* sKTh = smU + 8704;     // [d pair][t], reused as sATh
    uint32_t* sVh  = smU + 17408;    // [t pair][e]
    uint32_t* sPh  = smU + 22016;    // [f pair][e]
    float* sPden = (float*)(smU + 26624);
    float* sDen  = (float*)(smU + 26752);
    float* sCB   = (float*)(smU + 26880);
    float* sSB   = (float*)(smU + 26944);

    const int nh = blockIdx.x, c = blockIdx.y;
    const int n = nh >> 3, h = nh & 7;
    const int tid = threadIdx.x;
    const int wid = tid >> 5, lane = tid & 31;
    const int gid = lane >> 2, tid4 = lane & 3;

    if (tid < 128) sDen[tid] = 0.0f;
    if (tid >= 128 && tid < 192) {
        int di = tid - 128;
        float sb_, cb_;
        sincosf(pb[(h << 6) + di], &sb_, &cb_);
        sCB[di] = cb_; sSB[di] = sb_;
    }
    __syncthreads();

    // Phase 1a: features, packed (cos,sin) per half2
    for (int idx = tid; idx < 128*64; idx += 1024) {
        int t = idx >> 6, di = idx & 63;
        int tg = c * TCH + t;
        int gbase = ((n << 10) + tg) * DDIM + (h << 6) + di;
        float qv = g_Q[gbase], kv = g_K[gbase];
        float w  = pw[(h << 6) + di];
        float cf = coeff[(h << 6) + di];
        float sk, ck;
        sincosf((float)tg * w, &sk, &ck);
        float cb_ = sCB[di], sb_ = sSB[di];
        float cq = ck * cb_ - sk * sb_;
        float sq = sk * cb_ + ck * sb_;
        float qc = qv * cf;
        sQTh[di*SH + t] = pack_h2(qc * cq, qc * sq);
        sKTh[di*SH + t] = pack_h2(kv * ck, kv * sk);
    }
    // Phase 1a': V, packed pairs along t
    for (int idx = tid; idx < 64*64; idx += 1024) {
        int tp = idx >> 6, e = idx & 63;
        int gb = ((n << 10) + c * TCH + 2*tp) * DDIM + (h << 6) + e;
        float v0 = g_V[gb];
        float v1 = g_V[gb + DDIM];
        sVh[tp*SVH + e] = pack_h2(v0, v1);
    }
    // Phase 1b: inline prefix reduction, packed pairs along f (MLP batched)
    if (c > 0) {
        size_t sb = (size_t)nh * NCH * SROW;
        for (int idx = tid; idx < 64*64; idx += 1024) {
            int fp = idx >> 6, e = idx & 63;
            size_t i0 = sb + (size_t)(2*fp) * 64 + e;
            size_t i1 = i0 + 64;
            float a0 = g_S[i0], b0 = g_S[i1];
            float a1 = g_S[i0 + 1*SROW], b1 = g_S[i1 + 1*SROW];
            float a2 = g_S[i0 + 2*SROW], b2 = g_S[i1 + 2*SROW];
            float a3 = g_S[i0 + 3*SROW], b3 = g_S[i1 + 3*SROW];
            float a4 = g_S[i0 + 4*SROW], b4 = g_S[i1 + 4*SROW];
            float a5 = g_S[i0 + 5*SROW], b5 = g_S[i1 + 5*SROW];
            float a6 = g_S[i0 + 6*SROW], b6 = g_S[i1 + 6*SROW];
            float A = a0, B = b0;
            if (c > 1) { A += a1; B += b1; }
            if (c > 2) { A += a2; B += b2; }
            if (c > 3) { A += a3; B += b3; }
            if (c > 4) { A += a4; B += b4; }
            if (c > 5) { A += a5; B += b5; }
            if (c > 6) { A += a6; B += b6; }
            sPh[fp*SVH + e] = pack_h2(A, B);
        }
        if (tid < 128) {
            size_t i0 = sb + 8192 + tid;
            float v0 = g_S[i0];
            float v1 = g_S[i0 + 1*SROW];
            float v2 = g_S[i0 + 2*SROW];
            float v3 = g_S[i0 + 3*SROW];
            float v4 = g_S[i0 + 4*SROW];
            float v5 = g_S[i0 + 5*SROW];
            float v6 = g_S[i0 + 6*SROW];
            float a = v0;
            if (c > 1) a += v1;
            if (c > 2) a += v2;
            if (c > 3) a += v3;
            if (c > 4) a += v4;
            if (c > 5) a += v5;
            if (c > 6) a += v6;
            sPden[tid] = a;
        }
    }
    __syncthreads();

    // Phase 2: scores (128x128), 8 k16 steps, warp tile 32x16
    const int m2 = (wid & 3) * 32;
    const int n2 = (wid >> 2) * 16;
    float acc[2][2][4] = {};
#pragma unroll
    for (int s = 0; s < 8; s++) {
        const int kp0 = s * 8 + tid4, kp1 = kp0 + 4;
        uint32_t af[2][4];
#pragma unroll
        for (int mt = 0; mt < 2; mt++) {
            int r = m2 + mt * 16 + gid;
            af[mt][0] = sQTh[kp0*SH + r];
            af[mt][1] = sQTh[kp0*SH + r + 8];
            af[mt][2] = sQTh[kp1*SH + r];
            af[mt][3] = sQTh[kp1*SH + r + 8];
        }
        uint32_t bf[2][2];
#pragma unroll
        for (int nt = 0; nt < 2; nt++) {
            int nn = n2 + nt * 8 + gid;
            bf[nt][0] = sKTh[kp0*SH + nn];
            bf[nt][1] = sKTh[kp1*SH + nn];
        }
#pragma unroll
        for (int mt = 0; mt < 2; mt++)
#pragma unroll
            for (int nt = 0; nt < 2; nt++)
                mma_f16(acc[mt][nt], af[mt], bf[nt]);
    }
    __syncthreads();

    // Causal mask -> packed half2 col-pairs into sATh [t'pair][row], row sums
    uint32_t* sATh = sKTh;
#pragma unroll
    for (int mt = 0; mt < 2; mt++) {
        int r = m2 + mt * 16 + gid;
        float rs_lo = 0.0f, rs_hi = 0.0f;
#pragma unroll
        for (int nt = 0; nt < 2; nt++) {
            int cb = n2 + nt * 8 + tid4 * 2;
            int cbp = (cb >> 1);
            float v0 = (cb     <= r)     ? acc[mt][nt][0] : 0.0f;
            float v1 = (cb + 1 <= r)     ? acc[mt][nt][1] : 0.0f;
            float v2 = (cb     <= r + 8) ? acc[mt][nt][2] : 0.0f;
            float v3 = (cb + 1 <= r + 8) ? acc[mt][nt][3] : 0.0f;
            sATh[cbp*SH + r]     = pack_h2(v0, v1);
            sATh[cbp*SH + r + 8] = pack_h2(v2, v3);
            rs_lo += v0 + v1;
            rs_hi += v2 + v3;
        }
        atomicAdd(&sDen[r], rs_lo);
        atomicAdd(&sDen[r + 8], rs_hi);
    }
    __syncthreads();

    // Phase 3: out = A@V + PhiQ^T@P (128x64), tile 16x16
    const int m3 = (wid & 7) * 16;
    const int n3 = (wid >> 3) * 16;
    float o[2][4] = {};
#pragma unroll
    for (int s = 0; s < 8; s++) {
        const int kp0 = s * 8 + tid4, kp1 = kp0 + 4;
        uint32_t af[4];
        {
            int r = m3 + gid;
            af[0] = sATh[kp0*SH + r];
            af[1] = sATh[kp0*SH + r + 8];
            af[2] = sATh[kp1*SH + r];
            af[3] = sATh[kp1*SH + r + 8];
        }
        uint32_t bf[2][2];
#pragma unroll
        for (int nt = 0; nt < 2; nt++) {
            int nn = n3 + nt * 8 + gid;
            bf[nt][0] = sVh[kp0*SVH + nn];
            bf[nt][1] = sVh[kp1*SVH + nn];
        }
#pragma unroll
        for (int nt = 0; nt < 2; nt++)
            mma_f16(o[nt], af, bf[nt]);
    }
    if (c > 0) {
#pragma unroll
        for (int s = 0; s < 8; s++) {
            const int kp0 = s * 8 + tid4, kp1 = kp0 + 4;
            uint32_t af[4];
            {
                int r = m3 + gid;
                af[0] = sQTh[kp0*SH + r];
                af[1] = sQTh[kp0*SH + r + 8];
                af[2] = sQTh[kp1*SH + r];
                af[3] = sQTh[kp1*SH + r + 8];
            }
            uint32_t bf[2][2];
#pragma unroll
            for (int nt = 0; nt < 2; nt++) {
                int nn = n3 + nt * 8 + gid;
                bf[nt][0] = sPh[kp0*SVH + nn];
                bf[nt][1] = sPh[kp1*SVH + nn];
            }
#pragma unroll
            for (int nt = 0; nt < 2; nt++)
                mma_f16(o[nt], af, bf[nt]);
        }
        // den inter-chunk term (fp32, 8-way split over 64 f-pairs)
        int t = tid & 127, part = tid >> 7;
        float s = 0.0f;
        for (int fp = part * 8; fp < part * 8 + 8; fp++) {
            __half2 hv = *(__half2*)&sQTh[fp*SH + t];
            s += __low2float(hv) * sPden[2*fp] + __high2float(hv) * sPden[2*fp + 1];
        }
        atomicAdd(&sDen[t], s);
    }
    __syncthreads();

    // Phase 4: normalize + write (N, Lq, H*dh)
    {
        int r = m3 + gid;
        float inv_lo = 1.0f / sDen[r];
        float inv_hi = 1.0f / sDen[r + 8];
        int tg_lo = c * TCH + r;
        int tg_hi = tg_lo + 8;
#pragma unroll
        for (int nt = 0; nt < 2; nt++) {
            int e = n3 + nt * 8 + tid4 * 2;
            *(float2*)&out[((n << 10) + tg_lo) * DDIM + (h << 6) + e] =
                make_float2(o[nt][0] * inv_lo, o[nt][1] * inv_lo);
            *(float2*)&out[((n << 10) + tg_hi) * DDIM + (h << 6) + e] =
                make_float2(o[nt][2] * inv_hi, o[nt][3] * inv_hi);
        }
    }
}

// ---------------------------------------------------------------------------
extern "C" void kernel_launch(void* const* d_in, const int* in_sizes, int n_in,
                              void* d_out, int out_size) {
    const float* query = (const float*)d_in[0];
    const float* key   = (const float*)d_in[1];
    const float* Wq    = (const float*)d_in[2];
    const float* Wk    = (const float*)d_in[3];
    const float* Wv    = (const float*)d_in[4];
    const float* coeff = (const float*)d_in[5];
    const float* pw    = (const float*)d_in[6];
    const float* pb    = (const float*)d_in[7];
    float* out = (float*)d_out;

    cudaFuncSetAttribute(proj_mma_kernel,
                         cudaFuncAttributeMaxDynamicSharedMemorySize, 65536);
    cudaFuncSetAttribute(chunk_state_kernel,
                         cudaFuncAttributeMaxDynamicSharedMemorySize, 53248);
    cudaFuncSetAttribute(attn_out_kernel,
                         cudaFuncAttributeMaxDynamicSharedMemorySize, 108032);

    conv_half_kernel<<<dim3(1024, 5), 256>>>(query, key, Wq, Wk, Wv);
    proj_mma_kernel<<<dim3(MROWS/128, DDIM/128, 3), 256, 65536>>>();
    chunk_state_kernel<<<dim3(NHH, NCH-1), 512, 53248>>>(pw);
    attn_out_kernel<<<dim3(NHH, NCH), 1024, 108032>>>(pw, pb, coeff, out);
}